// round 1
// baseline (speedup 1.0000x reference)
#include <cuda_runtime.h>
#include <cstdint>

// Problem constants (fixed shapes from the reference)
constexpr int T = 8;
constexpr int N = 200000;
constexpr int D = 128;        // embedding dim (fp32) -> 512 bytes/row
constexpr int B = 8192;       // bags per table (power of 2)
constexpr int L = 163840;     // indices per table
constexpr int D4 = D / 4;     // 32 float4 per row; one per lane

// One warp handles one (table, bag) pair.
// lane l owns out columns [l*4, l*4+4) of the D=128 segment.
__global__ __launch_bounds__(256, 8)
void grouped_embedding_bag_kernel(const float* __restrict__ weights,   // [T, N, D]
                                  const int*   __restrict__ values,    // [T, L]
                                  const int*   __restrict__ offsets,   // [T, B+1]
                                  float*       __restrict__ out)       // [B, T*D]
{
    const int warp_global = (blockIdx.x * blockDim.x + threadIdx.x) >> 5;
    const int lane = threadIdx.x & 31;
    if (warp_global >= T * B) return;

    const int t = warp_global >> 13;        // / B  (B = 8192 = 2^13)
    const int b = warp_global & (B - 1);    // % B

    const int  start = offsets[t * (B + 1) + b];
    const int  end   = offsets[t * (B + 1) + b + 1];

    const float4* __restrict__ wt =
        reinterpret_cast<const float4*>(weights) + (size_t)t * N * D4;
    const int* __restrict__ vals = values + (size_t)t * L;

    float acc0 = 0.f, acc1 = 0.f, acc2 = 0.f, acc3 = 0.f;

    int i = start;
    // Unroll x4: 4 independent row gathers in flight per warp (MLP=4).
    for (; i + 4 <= end; i += 4) {
        const int r0 = vals[i + 0];
        const int r1 = vals[i + 1];
        const int r2 = vals[i + 2];
        const int r3 = vals[i + 3];
        const float4 v0 = wt[(size_t)r0 * D4 + lane];
        const float4 v1 = wt[(size_t)r1 * D4 + lane];
        const float4 v2 = wt[(size_t)r2 * D4 + lane];
        const float4 v3 = wt[(size_t)r3 * D4 + lane];
        acc0 += v0.x + v1.x + v2.x + v3.x;
        acc1 += v0.y + v1.y + v2.y + v3.y;
        acc2 += v0.z + v1.z + v2.z + v3.z;
        acc3 += v0.w + v1.w + v2.w + v3.w;
    }
    for (; i < end; ++i) {
        const int r = vals[i];
        const float4 v = wt[(size_t)r * D4 + lane];
        acc0 += v.x; acc1 += v.y; acc2 += v.z; acc3 += v.w;
    }

    // out[b, t*D + lane*4 .. +4)
    float4 result = make_float4(acc0, acc1, acc2, acc3);
    float4* __restrict__ out4 = reinterpret_cast<float4*>(out);
    out4[(size_t)b * (T * D4) + t * D4 + lane] = result;
}

extern "C" void kernel_launch(void* const* d_in, const int* in_sizes, int n_in,
                              void* d_out, int out_size)
{
    const float* weights = (const float*)d_in[0];   // [T, N, D] fp32
    const int*   values  = (const int*)d_in[1];     // [T, L] int32
    const int*   offsets = (const int*)d_in[2];     // [T, B+1] int32
    float*       out     = (float*)d_out;           // [B, T*D] fp32

    const int total_warps   = T * B;                // 65536
    const int threads       = 256;                  // 8 warps/block
    const int warps_per_blk = threads / 32;
    const int blocks        = (total_warps + warps_per_blk - 1) / warps_per_blk;

    grouped_embedding_bag_kernel<<<blocks, threads>>>(weights, values, offsets, out);
}

// round 2
// speedup vs baseline: 1.0639x; 1.0639x over previous
#include <cuda_runtime.h>
#include <cstdint>

// Problem constants (fixed shapes from the reference)
constexpr int T = 8;
constexpr int N = 200000;
constexpr int D = 128;        // embedding dim (fp32) -> 512 bytes/row
constexpr int B = 8192;       // bags per table (power of 2)
constexpr int L = 163840;     // indices per table
constexpr int D4 = D / 4;     // 32 float4 per row; one per lane
constexpr int UNROLL = 8;     // independent row gathers in flight per warp

// One warp handles one (table, bag) pair.
// lane l owns out columns [l*4, l*4+4) of the D=128 segment.
// Per iteration: 8 index loads batched, then 8 row loads batched (MLP=8),
// with tail handled by predication (no serial scalar tail).
__global__ __launch_bounds__(256)
void grouped_embedding_bag_kernel(const float* __restrict__ weights,   // [T, N, D]
                                  const int*   __restrict__ values,    // [T, L]
                                  const int*   __restrict__ offsets,   // [T, B+1]
                                  float*       __restrict__ out)       // [B, T*D]
{
    const int warp_global = (blockIdx.x * blockDim.x + threadIdx.x) >> 5;
    const int lane = threadIdx.x & 31;
    if (warp_global >= T * B) return;

    const int t = warp_global >> 13;        // / B  (B = 8192 = 2^13)
    const int b = warp_global & (B - 1);    // % B

    const int start = offsets[t * (B + 1) + b];
    const int end   = offsets[t * (B + 1) + b + 1];

    const float4* __restrict__ wt =
        reinterpret_cast<const float4*>(weights) + (size_t)t * N * D4;
    const int* __restrict__ vals = values + (size_t)t * L;

    float acc0 = 0.f, acc1 = 0.f, acc2 = 0.f, acc3 = 0.f;

    for (int i = start; i < end; i += UNROLL) {
        // Batch 1: all index loads issued together (independent).
        int idx[UNROLL];
        #pragma unroll
        for (int j = 0; j < UNROLL; ++j) {
            idx[j] = (i + j < end) ? vals[i + j] : -1;
        }
        // Batch 2: all row loads issued together (independent, MLP=UNROLL).
        float4 v[UNROLL];
        #pragma unroll
        for (int j = 0; j < UNROLL; ++j) {
            if (idx[j] >= 0) {
                v[j] = wt[(size_t)idx[j] * D4 + lane];
            } else {
                v[j] = make_float4(0.f, 0.f, 0.f, 0.f);
            }
        }
        // Accumulate.
        #pragma unroll
        for (int j = 0; j < UNROLL; ++j) {
            acc0 += v[j].x;
            acc1 += v[j].y;
            acc2 += v[j].z;
            acc3 += v[j].w;
        }
    }

    // out[b, t*D + lane*4 .. +4)
    float4 result = make_float4(acc0, acc1, acc2, acc3);
    float4* __restrict__ out4 = reinterpret_cast<float4*>(out);
    out4[(size_t)b * (T * D4) + t * D4 + lane] = result;
}

extern "C" void kernel_launch(void* const* d_in, const int* in_sizes, int n_in,
                              void* d_out, int out_size)
{
    const float* weights = (const float*)d_in[0];   // [T, N, D] fp32
    const int*   values  = (const int*)d_in[1];     // [T, L] int32
    const int*   offsets = (const int*)d_in[2];     // [T, B+1] int32
    float*       out     = (float*)d_out;           // [B, T*D] fp32

    const int total_warps   = T * B;                // 65536
    const int threads       = 256;                  // 8 warps/block
    const int warps_per_blk = threads / 32;
    const int blocks        = (total_warps + warps_per_blk - 1) / warps_per_blk;

    grouped_embedding_bag_kernel<<<blocks, threads>>>(weights, values, offsets, out);
}